// round 9
// baseline (speedup 1.0000x reference)
#include <cuda_runtime.h>
#include <cstdint>
#include <math.h>

#define BSN   100
#define CCH   640
#define W_IN  19
#define IMG   (W_IN * W_IN)           // 361
#define NW    5
#define P25   25
#define META_PER_BS (2 * CCH * P25)   // 32000
#define META_TOTAL  (BSN * META_PER_BS)

// ===========================================================================
// Fully fused kernel: one block per (b,s).
//   Phase 1: stream 1280 images (s then q) via cp.async, 16-img chunks,
//            3-buffer pipeline; pool each chunk -> meta (gmem) + smem tile.
//   Phase 2: norms + all-pairs cosine + max over q, straight from smem.
// ===========================================================================
#define THREADS 512
#define CH_IMGS 16
#define CH_FLOATS (CH_IMGS * IMG)        // 5776
#define CH_N4 (CH_FLOATS / 4)            // 1444 = 2*512 + 420
#define N_CHUNKS (2 * CCH / CH_IMGS)     // 80
#define NBUF 3
// dynamic smem: pooled[2*25*640] + sA[16*19*5] + 3 bufs[5776]
#define POOLED_FLOATS (2 * P25 * CCH)    // 32000
#define SA_FLOATS (CH_IMGS * W_IN * NW)  // 1520
#define SMEM_FLOATS (POOLED_FLOATS + SA_FLOATS + NBUF * CH_FLOATS) // 50848
#define SMEM_BYTES (SMEM_FLOATS * 4)     // 203392

__device__ __forceinline__ void cp_async16(unsigned int saddr, const void* gptr) {
    asm volatile("cp.async.cg.shared.global [%0], [%1], 16;\n"
                 :: "r"(saddr), "l"(gptr));
}
__device__ __forceinline__ void cp_commit() {
    asm volatile("cp.async.commit_group;\n");
}
template<int N>
__device__ __forceinline__ void cp_wait() {
    asm volatile("cp.async.wait_group %0;\n" :: "n"(N));
}
__device__ __forceinline__ unsigned int s2u(const void* p) {
    return (unsigned int)__cvta_generic_to_shared(p);
}

__global__ __launch_bounds__(THREADS, 1) void fused_kernel(
    const float* __restrict__ s_in,
    const float* __restrict__ q_in,
    float* __restrict__ out)
{
    extern __shared__ float sm[];
    float* __restrict__ pooled = sm;                       // [50][640]
    float* __restrict__ sA     = sm + POOLED_FLOATS;       // [16*19*5]
    float* __restrict__ bufs   = sm + POOLED_FLOATS + SA_FLOATS; // 3x5776

    const int bs  = blockIdx.x;
    const int tid = threadIdx.x;

    // ---------------- prefetch helper (inlined via lambda-less macro) ------
    // chunk ck covers global images [ck*16, ck*16+16): t = sel, c0 = channel
#define PREFETCH(CK)                                                         \
    do {                                                                     \
        const int _img0 = (CK) * CH_IMGS;                                    \
        const int _t = _img0 / CCH;                                          \
        const int _c0 = _img0 - _t * CCH;                                    \
        const float* __restrict__ _g =                                       \
            (_t ? q_in : s_in) + ((size_t)bs * CCH + _c0) * IMG;             \
        const float4* __restrict__ _g4 = (const float4*)_g;                  \
        unsigned int _s = s2u(bufs + ((CK) % NBUF) * CH_FLOATS);             \
        cp_async16(_s + tid * 16, _g4 + tid);                                \
        cp_async16(_s + (tid + THREADS) * 16, _g4 + tid + THREADS);          \
        if (tid < CH_N4 - 2 * THREADS)                                       \
            cp_async16(_s + (tid + 2 * THREADS) * 16, _g4 + tid + 2 * THREADS); \
        cp_commit();                                                         \
    } while (0)

    PREFETCH(0);
    PREFETCH(1);

#pragma unroll 1
    for (int ck = 0; ck < N_CHUNKS; ck++) {
        if (ck + 2 < N_CHUNKS) { PREFETCH(ck + 2); cp_wait<2>(); }
        else if (ck + 1 < N_CHUNKS) { cp_wait<1>(); }
        else { cp_wait<0>(); }
        __syncthreads();   // chunk ck data visible; prev stage B done with sA

        const float* __restrict__ cbuf = bufs + (ck % NBUF) * CH_FLOATS;

        // ---- stage A: column-bin each row. 304 tasks ----
        if (tid < CH_IMGS * W_IN) {
            const int m = tid / W_IN;
            const int r = tid - m * W_IN;
            const float* __restrict__ row = cbuf + m * IMG + r * W_IN;
            float rr[W_IN];
#pragma unroll
            for (int w = 0; w < W_IN; w++) rr[w] = row[w];
            const int BS_[NW] = {0, 3, 7, 11, 15};
            const int BE_[NW] = {4, 8, 12, 16, 19};
#pragma unroll
            for (int j = 0; j < NW; j++) {
                float v = 0.0f;
#pragma unroll
                for (int w = BS_[j]; w < BE_[j]; w++) v += rr[w];
                sA[tid * NW + j] = v;
            }
        }
        __syncthreads();

        // ---- stage B: row-bin + scale; write meta (gmem) + pooled (smem) --
        if (tid < CH_IMGS * P25) {
            const int m = tid / P25;
            const int o = tid - m * P25;
            const int i = o / NW;
            const int j = o - i * NW;
            const int rs = (19 * i) / 5;
            const int leni = (19 * i + 23) / 5 - rs;
            const int lenj = (19 * j + 23) / 5 - (19 * j) / 5;
            const float* __restrict__ a = sA + (m * W_IN + rs) * NW + j;
            float v = a[0] + a[1 * NW] + a[2 * NW] + a[3 * NW];
            if (leni == 5) v += a[4 * NW];
            const float invi = (leni == 4) ? 0.25f : 0.2f;
            const float invj = (lenj == 4) ? 0.25f : 0.2f;
            v = v * invi * invj;

            const int img0 = ck * CH_IMGS;          // global image index
            const int t = img0 / CCH;
            const int c0 = img0 - t * CCH;
            // meta: [ch][p], ch = img0 + m  (s then q, matches concat)
            out[(size_t)bs * META_PER_BS + (size_t)(img0 + m) * P25 + o] = v;
            // pooled smem: row = t*25 + o (p), col = channel
            pooled[(t * P25 + o) * CCH + (c0 + m)] = v;
        }
        // no trailing sync: next iteration's top sync covers sA/buf reuse
    }
    __syncthreads();   // pooled tile complete

    // =================== Phase 2: cosine + max (all from smem) ============
    __shared__ float sn[2 * P25];
    __shared__ float simbuf[P25 * P25];

    // ---- norms: 64 nids x 8 threads (warp-uniform; nid >= 50 dummy) ----
    {
        const int nid = tid >> 3;              // 0..63
        const int sub = tid & 7;
        const bool valid = (nid < 2 * P25);
        const int row = valid ? nid : 0;
        const float* __restrict__ f = pooled + (size_t)row * CCH;
        float v = 0.0f;
#pragma unroll
        for (int c4 = sub; c4 < CCH / 4; c4 += 8) {
            float4 x = ((const float4*)f)[c4];
            v += x.x * x.x + x.y * x.y + x.z * x.z + x.w * x.w;
        }
        v += __shfl_xor_sync(0xffffffffu, v, 4);
        v += __shfl_xor_sync(0xffffffffu, v, 2);
        v += __shfl_xor_sync(0xffffffffu, v, 1);
        if (valid && sub == 0) sn[nid] = sqrtf(v);
    }

    // ---- dots: 16 warps; warp w handles tiles {w, w+16} (25 tiles) ----
    {
        const int w = tid >> 5;
        const int lane = tid & 31;
#pragma unroll
        for (int tile = w; tile < P25; tile += 16) {
            const int pg = (tile / NW) * NW;
            const int qg = (tile % NW) * NW;

            float acc[NW][NW];
#pragma unroll
            for (int i = 0; i < NW; i++)
#pragma unroll
                for (int j = 0; j < NW; j++) acc[i][j] = 0.0f;

#pragma unroll
            for (int k = 0; k < CCH / 128; k++) {   // 5 iters, 128 c each
                const int c = k * 128 + lane * 4;
                float4 sv[NW], qv[NW];
#pragma unroll
                for (int i = 0; i < NW; i++)
                    sv[i] = *(const float4*)&pooled[(pg + i) * CCH + c];
#pragma unroll
                for (int j = 0; j < NW; j++)
                    qv[j] = *(const float4*)&pooled[(P25 + qg + j) * CCH + c];
#pragma unroll
                for (int i = 0; i < NW; i++)
#pragma unroll
                    for (int j = 0; j < NW; j++) {
                        float a = acc[i][j];
                        a = fmaf(sv[i].x, qv[j].x, a);
                        a = fmaf(sv[i].y, qv[j].y, a);
                        a = fmaf(sv[i].z, qv[j].z, a);
                        a = fmaf(sv[i].w, qv[j].w, a);
                        acc[i][j] = a;
                    }
            }
#pragma unroll
            for (int off = 16; off; off >>= 1)
#pragma unroll
                for (int i = 0; i < NW; i++)
#pragma unroll
                    for (int j = 0; j < NW; j++)
                        acc[i][j] += __shfl_down_sync(0xffffffffu, acc[i][j], off);

            if (lane == 0) {
#pragma unroll
                for (int i = 0; i < NW; i++)
#pragma unroll
                    for (int j = 0; j < NW; j++)
                        simbuf[(pg + i) * P25 + (qg + j)] = acc[i][j];
            }
        }
    }
    __syncthreads();

    // ---- divide by norms + max over q ----
    if (tid < P25) {
        const float snp = sn[tid];
        float m = -INFINITY;
#pragma unroll
        for (int q = 0; q < P25; q++) {
            float den = fmaxf(snp * sn[P25 + q], 1e-8f);
            m = fmaxf(m, simbuf[tid * P25 + q] / den);
        }
        out[META_TOTAL + bs * P25 + tid] = m;
    }
#undef PREFETCH
}

extern "C" void kernel_launch(void* const* d_in, const int* in_sizes, int n_in,
                              void* d_out, int out_size)
{
    const float* s_in = (const float*)d_in[0];
    const float* q_in = (const float*)d_in[1];
    float* out = (float*)d_out;

    static bool attr_set = false;
    if (!attr_set) {
        cudaFuncSetAttribute(fused_kernel,
                             cudaFuncAttributeMaxDynamicSharedMemorySize,
                             SMEM_BYTES);
        attr_set = true;
    }

    fused_kernel<<<BSN, THREADS, SMEM_BYTES>>>(s_in, q_in, out);
}

// round 10
// speedup vs baseline: 1.2493x; 1.2493x over previous
#include <cuda_runtime.h>
#include <cstdint>
#include <math.h>

#define BSN   100
#define CCH   640
#define W_IN  19
#define IMG   (W_IN * W_IN)           // 361
#define NW    5
#define P25   25
#define META_PER_BS (2 * CCH * P25)   // 32000
#define META_TOTAL  (BSN * META_PER_BS)

// Transposed pooled data: [bs][2][p][c]  (c contiguous)
__device__ float scratch_g[(size_t)BSN * 2 * P25 * CCH];   // 12.8 MB
// Order-encoded running maxima, one per output element
__device__ unsigned int enc_g[BSN * P25];                  // 2500

// ===========================================================================
// Kernel 1: adaptive avg pool 19x19 -> 5x5, cp.async pipelined (R8 design).
// 2000 blocks x 64 images, 4 chunks of 16, double-buffered smem.
// Blocks 0..19 additionally zero enc_g.
// ===========================================================================
#define IMGS_CHUNK 16
#define CHUNK_FLOATS (IMGS_CHUNK * IMG)    // 5776
#define CHUNK_N4 (CHUNK_FLOATS / 4)        // 1444
#define POOL_THREADS 128
#define POOL_FULL 11                       // 11*128=1408, rem 36
#define N_CHUNKS 4
#define POOL_SMEM_FLOATS (2 * CHUNK_FLOATS + IMGS_CHUNK * W_IN * NW) // 13072

__device__ __forceinline__ void cp_async16(unsigned int saddr, const void* gptr) {
    asm volatile("cp.async.cg.shared.global [%0], [%1], 16;\n"
                 :: "r"(saddr), "l"(gptr));
}
__device__ __forceinline__ void cp_commit() {
    asm volatile("cp.async.commit_group;\n");
}
template<int N>
__device__ __forceinline__ void cp_wait() {
    asm volatile("cp.async.wait_group %0;\n" :: "n"(N));
}
__device__ __forceinline__ unsigned int s2u(const void* p) {
    return (unsigned int)__cvta_generic_to_shared(p);
}

__global__ __launch_bounds__(POOL_THREADS, 4) void pool_kernel(
    const float* __restrict__ s_in,
    const float* __restrict__ q_in,
    float* __restrict__ out)
{
    extern __shared__ float psm[];
    float* __restrict__ buf0 = psm;
    float* __restrict__ buf1 = psm + CHUNK_FLOATS;
    float* __restrict__ sA   = psm + 2 * CHUNK_FLOATS;

    const int blk = blockIdx.x;                // 0..1999
    const int tid = threadIdx.x;

    // zero the atomic-max buffer (completes before this kernel ends)
    if (blk < 20) {
        const int idx = blk * POOL_THREADS + tid;
        if (idx < BSN * P25) enc_g[idx] = 0u;
    }

    const int sel = (blk >= 1000) ? 1 : 0;
    const int lblk = blk - sel * 1000;

    const float* __restrict__ gsrc =
        (sel ? q_in : s_in) + (size_t)lblk * (64 * IMG);

    const int img0 = lblk * 64;
    const int bs = img0 / CCH;
    const int c0 = img0 - bs * CCH;
    float* __restrict__ meta_base =
        out + (size_t)bs * META_PER_BS + (size_t)(sel * CCH + c0) * P25;
    float* __restrict__ scr_base =
        scratch_g + ((size_t)(bs * 2 + sel) * P25) * CCH;

    // ---- prefetch chunk 0 ----
    {
        const float4* g = (const float4*)(gsrc);
        unsigned int s = s2u(buf0);
#pragma unroll
        for (int k = 0; k < POOL_FULL; k++)
            cp_async16(s + (tid + k * POOL_THREADS) * 16,
                       g + tid + k * POOL_THREADS);
        if (tid < CHUNK_N4 - POOL_FULL * POOL_THREADS)
            cp_async16(s + (POOL_FULL * POOL_THREADS + tid) * 16,
                       g + POOL_FULL * POOL_THREADS + tid);
        cp_commit();
    }

#pragma unroll
    for (int ck = 0; ck < N_CHUNKS; ck++) {
        if (ck + 1 < N_CHUNKS) {
            const float4* g = (const float4*)(gsrc + (ck + 1) * CHUNK_FLOATS);
            unsigned int s = s2u(((ck + 1) & 1) ? buf1 : buf0);
#pragma unroll
            for (int k = 0; k < POOL_FULL; k++)
                cp_async16(s + (tid + k * POOL_THREADS) * 16,
                           g + tid + k * POOL_THREADS);
            if (tid < CHUNK_N4 - POOL_FULL * POOL_THREADS)
                cp_async16(s + (POOL_FULL * POOL_THREADS + tid) * 16,
                           g + POOL_FULL * POOL_THREADS + tid);
            cp_commit();
            cp_wait<1>();
        } else {
            cp_wait<0>();
        }
        __syncthreads();

        const float* __restrict__ cbuf = (ck & 1) ? buf1 : buf0;

        // ---- stage A: column-bin rows. 304 tasks ----
#pragma unroll
        for (int base = 0; base < IMGS_CHUNK * W_IN; base += POOL_THREADS) {
            const int idx = base + tid;
            if (idx < IMGS_CHUNK * W_IN) {
                const float* __restrict__ row = cbuf + idx * W_IN;
                float r[W_IN];
#pragma unroll
                for (int w = 0; w < W_IN; w++) r[w] = row[w];
                const int BS_[NW] = {0, 3, 7, 11, 15};
                const int BE_[NW] = {4, 8, 12, 16, 19};
#pragma unroll
                for (int j = 0; j < NW; j++) {
                    float v = 0.0f;
#pragma unroll
                    for (int w = BS_[j]; w < BE_[j]; w++) v += r[w];
                    sA[idx * NW + j] = v;
                }
            }
        }
        __syncthreads();

        // ---- stage B: row-bin + scale; write meta + scratch ----
        const int cc0 = c0 + ck * IMGS_CHUNK;
        float* __restrict__ mdst = meta_base + (size_t)ck * IMGS_CHUNK * P25;
#pragma unroll
        for (int base = 0; base < IMGS_CHUNK * P25; base += POOL_THREADS) {
            const int idx = base + tid;
            if (idx < IMGS_CHUNK * P25) {
                const int img = idx / P25;
                const int o = idx - img * P25;
                const int i = o / NW;
                const int j = o - i * NW;
                const int rs = (19 * i) / 5;
                const int leni = (19 * i + 23) / 5 - rs;
                const int lenj = (19 * j + 23) / 5 - (19 * j) / 5;
                const float* __restrict__ a = sA + (img * W_IN + rs) * NW + j;
                float v = a[0] + a[1 * NW] + a[2 * NW] + a[3 * NW];
                if (leni == 5) v += a[4 * NW];
                const float invi = (leni == 4) ? 0.25f : 0.2f;
                const float invj = (lenj == 4) ? 0.25f : 0.2f;
                v = v * invi * invj;
                mdst[idx] = v;
                scr_base[(size_t)o * CCH + cc0 + img] = v;
            }
        }
    }
}

// ===========================================================================
// Kernel 2: dots. 500 blocks = (bs, p-group); 5 warps = q-groups.
// No smem, no syncs. Each warp: 10 rows via LDG.128, dots + self-dots,
// warp reduce, per-p max over its 5 q, order-encoded atomicMax.
// ===========================================================================
#define DOT_THREADS 160

__device__ __forceinline__ unsigned int enc_f(float f) {
    int i = __float_as_int(f);
    return (i >= 0) ? ((unsigned int)i | 0x80000000u) : ~(unsigned int)i;
}

__global__ __launch_bounds__(DOT_THREADS) void dots_kernel(void)
{
    const int blk = blockIdx.x;        // 0..499
    const int bs = blk / NW;
    const int pg = (blk - bs * NW) * NW;
    const int w = threadIdx.x >> 5;    // 0..4
    const int lane = threadIdx.x & 31;
    const int qg = w * NW;

    const float* __restrict__ sbase =
        scratch_g + (size_t)(bs * 2 + 0) * P25 * CCH;
    const float* __restrict__ qbase =
        scratch_g + (size_t)(bs * 2 + 1) * P25 * CCH;

    float acc[NW][NW];
    float ssq[NW], qsq[NW];
#pragma unroll
    for (int i = 0; i < NW; i++) {
        ssq[i] = 0.0f; qsq[i] = 0.0f;
#pragma unroll
        for (int j = 0; j < NW; j++) acc[i][j] = 0.0f;
    }

#pragma unroll
    for (int k = 0; k < CCH / 128; k++) {    // 5 iters, 128 c each
        const int c = k * 128 + lane * 4;
        float4 sv[NW], qv[NW];
#pragma unroll
        for (int i = 0; i < NW; i++)
            sv[i] = *(const float4*)(sbase + (size_t)(pg + i) * CCH + c);
#pragma unroll
        for (int j = 0; j < NW; j++)
            qv[j] = *(const float4*)(qbase + (size_t)(qg + j) * CCH + c);
#pragma unroll
        for (int i = 0; i < NW; i++) {
            ssq[i] = fmaf(sv[i].x, sv[i].x, ssq[i]);
            ssq[i] = fmaf(sv[i].y, sv[i].y, ssq[i]);
            ssq[i] = fmaf(sv[i].z, sv[i].z, ssq[i]);
            ssq[i] = fmaf(sv[i].w, sv[i].w, ssq[i]);
        }
#pragma unroll
        for (int j = 0; j < NW; j++) {
            qsq[j] = fmaf(qv[j].x, qv[j].x, qsq[j]);
            qsq[j] = fmaf(qv[j].y, qv[j].y, qsq[j]);
            qsq[j] = fmaf(qv[j].z, qv[j].z, qsq[j]);
            qsq[j] = fmaf(qv[j].w, qv[j].w, qsq[j]);
        }
#pragma unroll
        for (int i = 0; i < NW; i++)
#pragma unroll
            for (int j = 0; j < NW; j++) {
                float a = acc[i][j];
                a = fmaf(sv[i].x, qv[j].x, a);
                a = fmaf(sv[i].y, qv[j].y, a);
                a = fmaf(sv[i].z, qv[j].z, a);
                a = fmaf(sv[i].w, qv[j].w, a);
                acc[i][j] = a;
            }
    }

    // warp reduction of 35 values
#pragma unroll
    for (int off = 16; off; off >>= 1) {
#pragma unroll
        for (int i = 0; i < NW; i++) {
            ssq[i] += __shfl_down_sync(0xffffffffu, ssq[i], off);
            qsq[i] += __shfl_down_sync(0xffffffffu, qsq[i], off);
#pragma unroll
            for (int j = 0; j < NW; j++)
                acc[i][j] += __shfl_down_sync(0xffffffffu, acc[i][j], off);
        }
    }

    if (lane == 0) {
        float qn[NW];
#pragma unroll
        for (int j = 0; j < NW; j++) qn[j] = sqrtf(qsq[j]);
#pragma unroll
        for (int i = 0; i < NW; i++) {
            const float snp = sqrtf(ssq[i]);
            float m = -INFINITY;
#pragma unroll
            for (int j = 0; j < NW; j++) {
                const float den = fmaxf(snp * qn[j], 1e-8f);
                m = fmaxf(m, acc[i][j] / den);
            }
            atomicMax(&enc_g[bs * P25 + pg + i], enc_f(m));
        }
    }
}

// ===========================================================================
// Kernel 3: decode encoded maxima into d_out.
// ===========================================================================
__global__ __launch_bounds__(256) void decode_kernel(float* __restrict__ out)
{
    const int idx = blockIdx.x * 256 + threadIdx.x;
    if (idx < BSN * P25) {
        const unsigned int u = enc_g[idx];
        const int i = (u & 0x80000000u) ? (int)(u & 0x7FFFFFFFu)
                                        : (int)~u;
        out[META_TOTAL + idx] = __int_as_float(i);
    }
}

extern "C" void kernel_launch(void* const* d_in, const int* in_sizes, int n_in,
                              void* d_out, int out_size)
{
    const float* s_in = (const float*)d_in[0];
    const float* q_in = (const float*)d_in[1];
    float* out = (float*)d_out;

    static bool attr_set = false;
    if (!attr_set) {
        cudaFuncSetAttribute(pool_kernel,
                             cudaFuncAttributeMaxDynamicSharedMemorySize,
                             POOL_SMEM_FLOATS * (int)sizeof(float));
        attr_set = true;
    }

    pool_kernel<<<2000, POOL_THREADS, POOL_SMEM_FLOATS * sizeof(float)>>>(
        s_in, q_in, out);
    dots_kernel<<<BSN * NW, DOT_THREADS>>>();
    decode_kernel<<<(BSN * P25 + 255) / 256, 256>>>(out);
}

// round 12
// speedup vs baseline: 1.3882x; 1.1112x over previous
#include <cuda_runtime.h>
#include <cstdint>
#include <math.h>

#define BSN   100
#define CCH   640
#define W_IN  19
#define IMG   (W_IN * W_IN)           // 361
#define NW    5
#define P25   25
#define META_PER_BS (2 * CCH * P25)   // 32000
#define META_TOTAL  (BSN * META_PER_BS)

// Transposed pooled data: [bs][2][p][c]  (c contiguous)
__device__ float scratch_g[(size_t)BSN * 2 * P25 * CCH];   // 12.8 MB

// ---------------------------------------------------------------------------
// PTX helpers: cp.async + st.global with L2 cache_hint policies
// ---------------------------------------------------------------------------
__device__ __forceinline__ unsigned long long mk_policy_ef() {
    unsigned long long p;
    asm("createpolicy.fractional.L2::evict_first.b64 %0, 1.0;" : "=l"(p));
    return p;
}
__device__ __forceinline__ unsigned long long mk_policy_el() {
    unsigned long long p;
    asm("createpolicy.fractional.L2::evict_last.b64 %0, 1.0;" : "=l"(p));
    return p;
}
__device__ __forceinline__ void cp_async16_ef(unsigned int saddr,
                                              const void* gptr,
                                              unsigned long long pol) {
    asm volatile("cp.async.cg.shared.global.L2::cache_hint [%0], [%1], 16, %2;\n"
                 :: "r"(saddr), "l"(gptr), "l"(pol));
}
__device__ __forceinline__ void cp_commit() {
    asm volatile("cp.async.commit_group;\n");
}
template<int N>
__device__ __forceinline__ void cp_wait() {
    asm volatile("cp.async.wait_group %0;\n" :: "n"(N));
}
__device__ __forceinline__ unsigned int s2u(const void* p) {
    return (unsigned int)__cvta_generic_to_shared(p);
}
__device__ __forceinline__ void stg_hint(float* p, float v,
                                         unsigned long long pol) {
    asm volatile("st.global.L2::cache_hint.f32 [%0], %1, %2;"
                 :: "l"(p), "f"(v), "l"(pol));
}

// ===========================================================================
// Kernel 1: adaptive avg pool 19x19 -> 5x5, cp.async pipelined.
// 2000 blocks x 64 images; 8 chunks of 8 images; double-buffered 26 KB smem
// (8 blocks/SM). Inputs: L2 evict_first. meta: evict_first. scratch: evict_last.
// ===========================================================================
#define IMGS_CHUNK 8
#define CHUNK_FLOATS (IMGS_CHUNK * IMG)    // 2888
#define CHUNK_N4 (CHUNK_FLOATS / 4)        // 722 = 5*128 + 82
#define POOL_THREADS 128
#define POOL_FULL 5
#define N_CHUNKS 8
#define SA_FLOATS (IMGS_CHUNK * W_IN * NW) // 760

__global__ __launch_bounds__(POOL_THREADS, 8) void pool_kernel(
    const float* __restrict__ s_in,
    const float* __restrict__ q_in,
    float* __restrict__ out)
{
    __shared__ float buf0[CHUNK_FLOATS];
    __shared__ float buf1[CHUNK_FLOATS];
    __shared__ float sA[SA_FLOATS];

    const int blk = blockIdx.x;                // 0..1999
    const int tid = threadIdx.x;
    const int sel = (blk >= 1000) ? 1 : 0;
    const int lblk = blk - sel * 1000;

    const unsigned long long pol_ef = mk_policy_ef();
    const unsigned long long pol_el = mk_policy_el();

    const float* __restrict__ gsrc =
        (sel ? q_in : s_in) + (size_t)lblk * (64 * IMG);

    const int img0 = lblk * 64;
    const int bs = img0 / CCH;
    const int c0 = img0 - bs * CCH;            // 64 | 640 => one bs per block
    float* __restrict__ meta_base =
        out + (size_t)bs * META_PER_BS + (size_t)(sel * CCH + c0) * P25;
    float* __restrict__ scr_base =
        scratch_g + ((size_t)(bs * 2 + sel) * P25) * CCH;

#define PF(CK, BUF)                                                          \
    do {                                                                     \
        const float4* _g = (const float4*)(gsrc + (CK) * CHUNK_FLOATS);      \
        unsigned int _s = s2u(BUF);                                          \
        _Pragma("unroll")                                                    \
        for (int _k = 0; _k < POOL_FULL; _k++)                               \
            cp_async16_ef(_s + (tid + _k * POOL_THREADS) * 16,               \
                          _g + tid + _k * POOL_THREADS, pol_ef);             \
        if (tid < CHUNK_N4 - POOL_FULL * POOL_THREADS)                       \
            cp_async16_ef(_s + (POOL_FULL * POOL_THREADS + tid) * 16,        \
                          _g + POOL_FULL * POOL_THREADS + tid, pol_ef);      \
        cp_commit();                                                         \
    } while (0)

    PF(0, buf0);

#pragma unroll
    for (int ck = 0; ck < N_CHUNKS; ck++) {
        if (ck + 1 < N_CHUNKS) {
            if ((ck + 1) & 1) PF(ck + 1, buf1); else PF(ck + 1, buf0);
            cp_wait<1>();
        } else {
            cp_wait<0>();
        }
        __syncthreads();

        const float* __restrict__ cbuf = (ck & 1) ? buf1 : buf0;

        // ---- stage A: column-bin rows. 152 tasks ----
        {
            const int idx = tid;
            if (idx < IMGS_CHUNK * W_IN) {
                const float* __restrict__ row = cbuf + idx * W_IN;
                float r[W_IN];
#pragma unroll
                for (int w = 0; w < W_IN; w++) r[w] = row[w];
                const int BS_[NW] = {0, 3, 7, 11, 15};
                const int BE_[NW] = {4, 8, 12, 16, 19};
#pragma unroll
                for (int j = 0; j < NW; j++) {
                    float v = 0.0f;
#pragma unroll
                    for (int w = BS_[j]; w < BE_[j]; w++) v += r[w];
                    sA[idx * NW + j] = v;
                }
            }
            const int idx2 = tid + POOL_THREADS;
            if (idx2 < IMGS_CHUNK * W_IN) {
                const float* __restrict__ row = cbuf + idx2 * W_IN;
                float r[W_IN];
#pragma unroll
                for (int w = 0; w < W_IN; w++) r[w] = row[w];
                const int BS_[NW] = {0, 3, 7, 11, 15};
                const int BE_[NW] = {4, 8, 12, 16, 19};
#pragma unroll
                for (int j = 0; j < NW; j++) {
                    float v = 0.0f;
#pragma unroll
                    for (int w = BS_[j]; w < BE_[j]; w++) v += r[w];
                    sA[idx2 * NW + j] = v;
                }
            }
        }
        __syncthreads();

        // ---- stage B: row-bin + scale; meta (evict_first) + scratch
        //      (evict_last). 200 tasks ----
        const int cc0 = c0 + ck * IMGS_CHUNK;
        float* __restrict__ mdst = meta_base + (size_t)ck * IMGS_CHUNK * P25;
#pragma unroll
        for (int base = 0; base < IMGS_CHUNK * P25; base += POOL_THREADS) {
            const int idx = base + tid;
            if (idx < IMGS_CHUNK * P25) {
                const int img = idx / P25;
                const int o = idx - img * P25;
                const int i = o / NW;
                const int j = o - i * NW;
                const int rs = (19 * i) / 5;
                const int leni = (19 * i + 23) / 5 - rs;
                const int lenj = (19 * j + 23) / 5 - (19 * j) / 5;
                const float* __restrict__ a = sA + (img * W_IN + rs) * NW + j;
                float v = a[0] + a[1 * NW] + a[2 * NW] + a[3 * NW];
                if (leni == 5) v += a[4 * NW];
                const float invi = (leni == 4) ? 0.25f : 0.2f;
                const float invj = (lenj == 4) ? 0.25f : 0.2f;
                v = v * invi * invj;
                stg_hint(mdst + idx, v, pol_ef);
                stg_hint(scr_base + (size_t)o * CCH + cc0 + img, v, pol_el);
            }
        }
    }
#undef PF
}

// ===========================================================================
// Kernel 2: dots. 500 blocks = (bs, p-group); 5 warps = q-groups.
// In-block smem max reduce (no atomics, no decode kernel).
// Scratch rows should be L2-resident (evict_last).
// ===========================================================================
#define DOT_THREADS 160

__global__ __launch_bounds__(DOT_THREADS) void dots_kernel(
    float* __restrict__ out)
{
    __shared__ float pmax[NW][NW];     // [warp(qg)][i]

    const int blk = blockIdx.x;        // 0..499
    const int bs = blk / NW;
    const int pg = (blk - bs * NW) * NW;
    const int w = threadIdx.x >> 5;    // 0..4
    const int lane = threadIdx.x & 31;
    const int qg = w * NW;

    const float* __restrict__ sbase =
        scratch_g + (size_t)(bs * 2 + 0) * P25 * CCH;
    const float* __restrict__ qbase =
        scratch_g + (size_t)(bs * 2 + 1) * P25 * CCH;

    float acc[NW][NW];
    float ssq[NW], qsq[NW];
#pragma unroll
    for (int i = 0; i < NW; i++) {
        ssq[i] = 0.0f; qsq[i] = 0.0f;
#pragma unroll
        for (int j = 0; j < NW; j++) acc[i][j] = 0.0f;
    }

#pragma unroll
    for (int k = 0; k < CCH / 128; k++) {    // 5 iters, 128 c each
        const int c = k * 128 + lane * 4;
        float4 sv[NW], qv[NW];
#pragma unroll
        for (int i = 0; i < NW; i++)
            sv[i] = *(const float4*)(sbase + (size_t)(pg + i) * CCH + c);
#pragma unroll
        for (int j = 0; j < NW; j++)
            qv[j] = *(const float4*)(qbase + (size_t)(qg + j) * CCH + c);
#pragma unroll
        for (int i = 0; i < NW; i++) {
            ssq[i] = fmaf(sv[i].x, sv[i].x, ssq[i]);
            ssq[i] = fmaf(sv[i].y, sv[i].y, ssq[i]);
            ssq[i] = fmaf(sv[i].z, sv[i].z, ssq[i]);
            ssq[i] = fmaf(sv[i].w, sv[i].w, ssq[i]);
        }
#pragma unroll
        for (int j = 0; j < NW; j++) {
            qsq[j] = fmaf(qv[j].x, qv[j].x, qsq[j]);
            qsq[j] = fmaf(qv[j].y, qv[j].y, qsq[j]);
            qsq[j] = fmaf(qv[j].z, qv[j].z, qsq[j]);
            qsq[j] = fmaf(qv[j].w, qv[j].w, qsq[j]);
        }
#pragma unroll
        for (int i = 0; i < NW; i++)
#pragma unroll
            for (int j = 0; j < NW; j++) {
                float a = acc[i][j];
                a = fmaf(sv[i].x, qv[j].x, a);
                a = fmaf(sv[i].y, qv[j].y, a);
                a = fmaf(sv[i].z, qv[j].z, a);
                a = fmaf(sv[i].w, qv[j].w, a);
                acc[i][j] = a;
            }
    }

    // warp reduction of 35 values
#pragma unroll
    for (int off = 16; off; off >>= 1) {
#pragma unroll
        for (int i = 0; i < NW; i++) {
            ssq[i] += __shfl_down_sync(0xffffffffu, ssq[i], off);
            qsq[i] += __shfl_down_sync(0xffffffffu, qsq[i], off);
#pragma unroll
            for (int j = 0; j < NW; j++)
                acc[i][j] += __shfl_down_sync(0xffffffffu, acc[i][j], off);
        }
    }

    if (lane == 0) {
        float qn[NW];
#pragma unroll
        for (int j = 0; j < NW; j++) qn[j] = sqrtf(qsq[j]);
#pragma unroll
        for (int i = 0; i < NW; i++) {
            const float snp = sqrtf(ssq[i]);
            float m = -INFINITY;
#pragma unroll
            for (int j = 0; j < NW; j++) {
                const float den = fmaxf(snp * qn[j], 1e-8f);
                m = fmaxf(m, acc[i][j] / den);
            }
            pmax[w][i] = m;
        }
    }
    __syncthreads();

    // final: 5 threads combine the 5 warps' partial maxima
    if (threadIdx.x < NW) {
        const int i = threadIdx.x;
        float m = pmax[0][i];
#pragma unroll
        for (int ww = 1; ww < NW; ww++) m = fmaxf(m, pmax[ww][i]);
        out[META_TOTAL + bs * P25 + pg + i] = m;
    }
}

extern "C" void kernel_launch(void* const* d_in, const int* in_sizes, int n_in,
                              void* d_out, int out_size)
{
    const float* s_in = (const float*)d_in[0];
    const float* q_in = (const float*)d_in[1];
    float* out = (float*)d_out;

    pool_kernel<<<2000, POOL_THREADS>>>(s_in, q_in, out);
    dots_kernel<<<BSN * NW, DOT_THREADS>>>(out);
}